// round 16
// baseline (speedup 1.0000x reference)
#include <cuda_runtime.h>
#include <cuda_fp16.h>
#include <math_constants.h>

// ---------------------------------------------------------------------------
// Quantization4bit, single persistent kernel with DYNAMIC WORK STEALING:
//   prologue: run-epoch from monotonic g_start; build the 256-cell LUT
//             (x32-replicated, bank==lane, conflict-free), codebook-only.
//   phase 1:  blocks steal 2048-float4 chunks (monotonic g_c1, quota
//             base = epoch*(C+2*NBLK)); per-chunk min/max, unroll-4.
//   barrier:  monotonic counter/epoch (replay-safe).
//   phase 2:  blocks steal chunks from g_c2; normalize + LUT lookup.
//             Midpoint recomputed as 0.5f*(f32(lo)+f32(hi)) — identical fp32
//             ops as the reference chain => bit-exact (fp32 |.| argmin,
//             first-min tie-break). Work assignment varies across replays but
//             chunk->output mapping is fixed and min/max is commutative =>
//             deterministic results.
// 592 blocks x 256 thr, 4 blocks/SM co-resident => spin barrier safe.
// ---------------------------------------------------------------------------

#define MAX_CB 16
#define NBLK 592
#define NTHR 256
#define NCELL 256
#define CHUNK 2048              // float4s per chunk (n4 = 2^21 = 1024 chunks)

__device__ float g_pmin[NBLK];
__device__ float g_pmax[NBLK];
__device__ float g_final_min;
__device__ float g_final_max;
__device__ unsigned g_start = 0;     // run-epoch counter (monotonic)
__device__ unsigned g_c1 = 0;        // phase-1 chunk counter (monotonic)
__device__ unsigned g_c2 = 0;        // phase-2 chunk counter (monotonic)
__device__ unsigned g_counter = 0;   // barrier arrivals (monotonic)
__device__ unsigned g_release = 0;   // barrier release epoch (monotonic)

__device__ __forceinline__ int cell_of(float xn) {
    float u = fmaf(xn, (float)(NCELL / 2), (float)(NCELL / 2));  // >= 0 by construction
    u = fminf(u, (float)(NCELL - 1));
    return (int)u;
}

__device__ __forceinline__ float lut_pick(unsigned e, float xn) {
    float lo = __half2float(__ushort_as_half((unsigned short)(e & 0xFFFFu)));
    float hi = __half2float(__ushort_as_half((unsigned short)(e >> 16)));
    float mid = 0.5f * (lo + hi);   // exact same computation as reference mid[]
    // strict > : exact-midpoint ties go to the LOWER index,
    // matching argmin's first-minimum tie-break.
    return (xn > mid) ? hi : lo;
}

__device__ __forceinline__ void mm4(float4 v, float& mn, float& mx) {
    mn = fminf(mn, fminf(fminf(v.x, v.y), fminf(v.z, v.w)));
    mx = fmaxf(mx, fmaxf(fmaxf(v.x, v.y), fmaxf(v.z, v.w)));
}

__device__ __forceinline__ float4 quant4(float4 v, float xmin, float inv,
                                         const unsigned* s_tbl, int lane) {
    float a[4] = {v.x, v.y, v.z, v.w};
    float r[4];
    #pragma unroll
    for (int k = 0; k < 4; k++) {
        float xn = fmaf((a[k] - xmin) * inv, 2.0f, -1.0f);
        unsigned e = s_tbl[(cell_of(xn) << 5) | lane];   // bank == lane
        r[k] = lut_pick(e, xn);
    }
    return make_float4(r[0], r[1], r[2], r[3]);
}

__global__ void __launch_bounds__(NTHR, 4)
q4_fused_kernel(const float4* __restrict__ x,
                const float* __restrict__ cb, int n_cb,
                float4* __restrict__ out, int n4) {
    __shared__ unsigned s_tbl[NCELL * 32];   // x32 replicated, bank == lane
    __shared__ float s_red[NTHR / 32];
    __shared__ float s_red2[NTHR / 32];
    __shared__ int s_ck[2];                  // double-buffered stolen chunk id
    __shared__ unsigned s_ep;
    __shared__ int s_last;

    const int lane = threadIdx.x & 31;
    const int warp = threadIdx.x >> 5;
    const int nchunks = n4 / CHUNK;          // 1024 (n4 divisible by CHUNK)

    // ------------------ run epoch ------------------
    if (threadIdx.x == 0) {
        unsigned old = atomicAdd(&g_start, 1u);
        s_ep = old / NBLK;
    }

    // ------- prologue: build the LUT (codebook-only) ----------------------
    {
        float c[MAX_CB];
        #pragma unroll
        for (int k = 0; k < MAX_CB; k++)
            c[k] = (k < n_cb) ? cb[k] : CUDART_INF_F;
        float mid[MAX_CB - 1];
        #pragma unroll
        for (int j = 0; j < MAX_CB - 1; j++)
            mid[j] = (j + 1 < n_cb) ? 0.5f * (c[j] + c[j + 1]) : CUDART_INF_F;

        // each thread owns exactly one cell (NTHR == NCELL)
        int cell = threadIdx.x;
        float xc = ((float)cell + 0.5f) * (2.0f / NCELL) - 1.0f;
        float val = c[0];
        #pragma unroll
        for (int j = 0; j < MAX_CB - 1; j++)
            val = (xc > mid[j]) ? c[j + 1] : val;
        float lo = val, hi = val;
        #pragma unroll
        for (int j = 0; j < MAX_CB - 1; j++) {
            if (j + 1 < n_cb && cell_of(mid[j]) == cell) {
                lo = c[j];
                hi = c[j + 1];
            }
        }
        __half2 pr = __floats2half2_rn(lo, hi);  // exact: fp16-originated
        unsigned pk = *(unsigned*)&pr;
        #pragma unroll
        for (int r = 0; r < 32; r++)
            s_tbl[(cell << 5) | ((r + lane) & 31)] = pk;
    }
    __syncthreads();

    const unsigned epoch = s_ep;
    const unsigned quota_base = epoch * (unsigned)(0 /*placeholder*/ + nchunks + 2 * NBLK);

    // ---------------- phase 1: work-stolen min/max ----------------
    float lmin = CUDART_INF_F;
    float lmax = -CUDART_INF_F;

    if (threadIdx.x == 0)
        s_ck[0] = (int)(atomicAdd(&g_c1, 1u) - quota_base);
    __syncthreads();

    {
        int buf = 0;
        for (;;) {
            int ck = s_ck[buf];
            if (threadIdx.x == 0)
                s_ck[buf ^ 1] = (int)(atomicAdd(&g_c1, 1u) - quota_base);
            if (ck >= nchunks) break;

            int b = ck * CHUNK + threadIdx.x;
            float4 v0 = __ldcg(&x[b]);
            float4 v1 = __ldcg(&x[b + NTHR]);
            float4 v2 = __ldcg(&x[b + 2 * NTHR]);
            float4 v3 = __ldcg(&x[b + 3 * NTHR]);
            float4 v4 = __ldcg(&x[b + 4 * NTHR]);
            float4 v5 = __ldcg(&x[b + 5 * NTHR]);
            float4 v6 = __ldcg(&x[b + 6 * NTHR]);
            float4 v7 = __ldcg(&x[b + 7 * NTHR]);
            mm4(v0, lmin, lmax); mm4(v1, lmin, lmax);
            mm4(v2, lmin, lmax); mm4(v3, lmin, lmax);
            mm4(v4, lmin, lmax); mm4(v5, lmin, lmax);
            mm4(v6, lmin, lmax); mm4(v7, lmin, lmax);

            __syncthreads();   // s_ck[buf^1] now visible to all
            buf ^= 1;
        }
    }

    #pragma unroll
    for (int o = 16; o > 0; o >>= 1) {
        lmin = fminf(lmin, __shfl_xor_sync(0xFFFFFFFFu, lmin, o));
        lmax = fmaxf(lmax, __shfl_xor_sync(0xFFFFFFFFu, lmax, o));
    }
    if (lane == 0) { s_red[warp] = lmin; s_red2[warp] = lmax; }
    __syncthreads();

    if (threadIdx.x == 0) {
        float bmin = s_red[0], bmax = s_red2[0];
        #pragma unroll
        for (int w = 1; w < NTHR / 32; w++) {
            bmin = fminf(bmin, s_red[w]);
            bmax = fmaxf(bmax, s_red2[w]);
        }
        g_pmin[blockIdx.x] = bmin;
        g_pmax[blockIdx.x] = bmax;
        __threadfence();
        unsigned old = atomicAdd(&g_counter, 1u);
        s_last = ((old % NBLK) == NBLK - 1);
    }
    __syncthreads();

    if (s_last) {
        float bmin = CUDART_INF_F, bmax = -CUDART_INF_F;
        for (int j = threadIdx.x; j < NBLK; j += NTHR) {
            bmin = fminf(bmin, g_pmin[j]);
            bmax = fmaxf(bmax, g_pmax[j]);
        }
        #pragma unroll
        for (int o = 16; o > 0; o >>= 1) {
            bmin = fminf(bmin, __shfl_xor_sync(0xFFFFFFFFu, bmin, o));
            bmax = fmaxf(bmax, __shfl_xor_sync(0xFFFFFFFFu, bmax, o));
        }
        if (lane == 0) { s_red[warp] = bmin; s_red2[warp] = bmax; }
        __syncthreads();
        if (threadIdx.x == 0) {
            float fmn = s_red[0], fmx = s_red2[0];
            #pragma unroll
            for (int w = 1; w < NTHR / 32; w++) {
                fmn = fminf(fmn, s_red[w]);
                fmx = fmaxf(fmx, s_red2[w]);
            }
            g_final_min = fmn;
            g_final_max = fmx;
            __threadfence();
            atomicAdd(&g_release, 1u);
        }
        __syncthreads();
    } else {
        if (threadIdx.x == 0) {
            while (*((volatile unsigned*)&g_release) < epoch + 1u)
                __nanosleep(64);
        }
        __syncthreads();
    }
    __threadfence();  // acquire for g_final_min/max

    const float xmin = g_final_min;
    const float xmax = g_final_max;
    const float inv = 1.0f / (xmax - xmin);

    // ---------------- phase 2: work-stolen quantize ----------------
    if (threadIdx.x == 0)
        s_ck[0] = (int)(atomicAdd(&g_c2, 1u) - quota_base);
    __syncthreads();

    {
        int buf = 0;
        for (;;) {
            int ck = s_ck[buf];
            if (threadIdx.x == 0)
                s_ck[buf ^ 1] = (int)(atomicAdd(&g_c2, 1u) - quota_base);
            if (ck >= nchunks) break;

            int b = ck * CHUNK + threadIdx.x;
            // group 1: 4 front-batched float4s
            float4 v0 = __ldcg(&x[b]);
            float4 v1 = __ldcg(&x[b + NTHR]);
            float4 v2 = __ldcg(&x[b + 2 * NTHR]);
            float4 v3 = __ldcg(&x[b + 3 * NTHR]);
            // group 2 issued early for MLP
            float4 v4 = __ldcg(&x[b + 4 * NTHR]);
            float4 v5 = __ldcg(&x[b + 5 * NTHR]);
            float4 v6 = __ldcg(&x[b + 6 * NTHR]);
            float4 v7 = __ldcg(&x[b + 7 * NTHR]);

            __stcs(&out[b], quant4(v0, xmin, inv, s_tbl, lane));
            __stcs(&out[b + NTHR], quant4(v1, xmin, inv, s_tbl, lane));
            __stcs(&out[b + 2 * NTHR], quant4(v2, xmin, inv, s_tbl, lane));
            __stcs(&out[b + 3 * NTHR], quant4(v3, xmin, inv, s_tbl, lane));
            __stcs(&out[b + 4 * NTHR], quant4(v4, xmin, inv, s_tbl, lane));
            __stcs(&out[b + 5 * NTHR], quant4(v5, xmin, inv, s_tbl, lane));
            __stcs(&out[b + 6 * NTHR], quant4(v6, xmin, inv, s_tbl, lane));
            __stcs(&out[b + 7 * NTHR], quant4(v7, xmin, inv, s_tbl, lane));

            __syncthreads();   // s_ck[buf^1] now visible to all
            buf ^= 1;
        }
    }

    // handle any tail elements not covered by whole chunks (none when
    // n4 % CHUNK == 0, but keep it correct for general sizes)
    int tail_start = nchunks * CHUNK;
    for (int p = tail_start + blockIdx.x * NTHR + threadIdx.x; p < n4;
         p += NBLK * NTHR) {
        float4 v = __ldcg(&x[p]);
        __stcs(&out[p], quant4(v, xmin, inv, s_tbl, lane));
    }
}

extern "C" void kernel_launch(void* const* d_in, const int* in_sizes, int n_in,
                              void* d_out, int out_size) {
    const float4* x = (const float4*)d_in[0];
    const float* cb = (const float*)d_in[1];
    float4* out = (float4*)d_out;

    int n = in_sizes[0];      // 8388608
    int n_cb = in_sizes[1];   // 14
    if (n_cb > MAX_CB) n_cb = MAX_CB;
    int n4 = n >> 2;

    q4_fused_kernel<<<NBLK, NTHR>>>(x, cb, n_cb, out, n4);
}